// round 1
// baseline (speedup 1.0000x reference)
#include <cuda_runtime.h>
#include <cstdint>

// Problem constants (B, D, T, K) from reference setup_inputs
#define Bq 8
#define Dd 256
#define Tt 2048
#define Kk 8192
#define NQ (Bq * Tt)          // 16384 queries
#define NEL (Bq * Dd * Tt)    // 4194304 z elements

// Scratch (device globals: no allocation allowed in kernel_launch)
__device__ unsigned long long g_keys[NQ];   // packed (dist_bits<<32)|index per query
__device__ float g_zz[NQ];                  // ||z_i||^2, fp32 sequential accumulation
__device__ float g_cc[Kk];                  // ||c_k||^2
__device__ double g_loss_sum;               // sum of (z_q - z)^2 in double

// ---------------------------------------------------------------------------
__global__ void init_kernel() {
    int i = blockIdx.x * blockDim.x + threadIdx.x;
    if (i < NQ) g_keys[i] = ~0ull;
    if (i == 0) g_loss_sum = 0.0;
}

// zz[i] = sum_d z[b][d][t]^2, sequential fp32, mul then add (no FMA contraction)
// to mimic XLA's elementwise-square-then-reduce in fp32.
__global__ void zz_kernel(const float* __restrict__ z) {
    int i = blockIdx.x * blockDim.x + threadIdx.x;
    if (i >= NQ) return;
    int b = i / Tt, t = i % Tt;
    const float* p = z + (size_t)b * Dd * Tt + t;
    float acc = 0.0f;
    for (int d = 0; d < Dd; d++) {
        float v = p[(size_t)d * Tt];
        acc = __fadd_rn(acc, __fmul_rn(v, v));
    }
    g_zz[i] = acc;
}

// cc[k] = sum_d c[k][d]^2 (its rounding is irrelevant at the final ulp grid,
// but keep sequential fp32 anyway).
__global__ void cc_kernel(const float* __restrict__ cb) {
    int k = blockIdx.x * blockDim.x + threadIdx.x;
    if (k >= Kk) return;
    const float* p = cb + (size_t)k * Dd;
    float acc = 0.0f;
    for (int d = 0; d < Dd; d++) {
        float v = p[d];
        acc = __fadd_rn(acc, __fmul_rn(v, v));
    }
    g_cc[k] = acc;
}

// ---------------------------------------------------------------------------
// Tiled fp32 GEMM (queries x codes) with fused argmin epilogue.
// BM=128 queries, BN=128 codes, BK=16 dims, 256 threads, 8x8 per-thread tile.
__global__ void __launch_bounds__(256) gemm_argmin_kernel(
    const float* __restrict__ z, const float* __restrict__ cb) {
    __shared__ float As[16][132];   // [dim][query], padded
    __shared__ float Bs[16][132];   // [dim][code], padded
    __shared__ unsigned long long skey[128];

    int tid = threadIdx.x;
    int tx = tid & 15, ty = tid >> 4;
    int k0 = blockIdx.x * 128;
    int i0 = blockIdx.y * 128;
    int b = i0 / Tt, t0 = i0 % Tt;      // 128 | T, so one b per block
    const float* zb = z + (size_t)b * Dd * Tt + t0;

    float acc[8][8];
    #pragma unroll
    for (int a = 0; a < 8; a++)
        #pragma unroll
        for (int c = 0; c < 8; c++) acc[a][c] = 0.0f;

    for (int d0 = 0; d0 < Dd; d0 += 16) {
        #pragma unroll
        for (int r = 0; r < 8; r++) {
            int e = tid + r * 256;
            int dA = e >> 7, ii = e & 127;              // A: 16 dims x 128 queries
            As[dA][ii] = zb[(size_t)(d0 + dA) * Tt + ii];
            int kkB = e >> 4, dB = e & 15;              // B: 128 codes x 16 dims
            Bs[dB][kkB] = cb[(size_t)(k0 + kkB) * Dd + d0 + dB];
        }
        __syncthreads();
        #pragma unroll
        for (int d = 0; d < 16; d++) {
            float af[8], bf[8];
            #pragma unroll
            for (int j = 0; j < 8; j++) af[j] = As[d][ty * 8 + j];
            #pragma unroll
            for (int j = 0; j < 8; j++) bf[j] = Bs[d][tx * 8 + j];
            #pragma unroll
            for (int a = 0; a < 8; a++)
                #pragma unroll
                for (int c = 0; c < 8; c++)
                    acc[a][c] = fmaf(af[a], bf[c], acc[a][c]);
        }
        __syncthreads();
    }

    // Epilogue: d = fl(fl(zz + (-2*dot)) + cc)  — replicates reference fp32
    // rounding sequence. d > 0 always (|z-c|^2 ~ 256) so float bits order as
    // uints; pack (bits<<32)|k so u64-min == (min d, then min index).
    if (tid < 128) skey[tid] = ~0ull;
    __syncthreads();
    #pragma unroll
    for (int a = 0; a < 8; a++) {
        int i = i0 + ty * 8 + a;
        float zzv = g_zz[i];
        unsigned long long best = ~0ull;
        #pragma unroll
        for (int c = 0; c < 8; c++) {
            int k = k0 + tx * 8 + c;
            float m2 = -2.0f * acc[a][c];               // exact (power of 2)
            float t1 = __fadd_rn(zzv, m2);
            float dd = __fadd_rn(t1, g_cc[k]);
            unsigned long long key =
                ((unsigned long long)__float_as_uint(dd) << 32) | (unsigned)k;
            if (key < best) best = key;
        }
        atomicMin(&skey[ty * 8 + a], best);
    }
    __syncthreads();
    if (tid < 128) atomicMin(&g_keys[i0 + tid], skey[tid]);
}

// ---------------------------------------------------------------------------
// Gather codebook rows, write z_q_st = fl(z + fl(z_q - z)), accumulate loss.
__global__ void gather_kernel(const float* __restrict__ z,
                              const float* __restrict__ cb,
                              float* __restrict__ out, int out_size) {
    __shared__ double ssum[256];
    int id = blockIdx.x * blockDim.x + threadIdx.x;
    double local = 0.0;
    if (id < NEL) {
        int t = id % Tt;
        int d = (id / Tt) % Dd;
        int b = id / (Tt * Dd);
        int i = b * Tt + t;
        int idx = (int)(unsigned)(g_keys[i] & 0xffffffffu);
        float zv = z[id];
        float zq = cb[(size_t)idx * Dd + d];
        float diff = __fadd_rn(zq, -zv);                 // fl(z_q - z)
        if (id < out_size) out[id] = __fadd_rn(zv, diff);// fl(z + diff)
        local = (double)__fmul_rn(diff, diff);
    }
    ssum[threadIdx.x] = local;
    __syncthreads();
    for (int s = 128; s > 0; s >>= 1) {
        if (threadIdx.x < s) ssum[threadIdx.x] += ssum[threadIdx.x + s];
        __syncthreads();
    }
    if (threadIdx.x == 0) atomicAdd(&g_loss_sum, ssum[0]);
}

__global__ void finalize_kernel(float* __restrict__ out, int out_size) {
    int i = blockIdx.x * blockDim.x + threadIdx.x;
    if (out_size >= NEL + NQ && i < NQ)
        out[NEL + i] = (float)(unsigned)(g_keys[i] & 0xffffffffu);
    if (i == 0 && out_size >= NEL + NQ + 1) {
        float m = (float)(g_loss_sum / (double)NEL);
        // loss = codebook_loss + 0.1 * commitment  (same mean both terms)
        out[NEL + NQ] = __fadd_rn(m, __fmul_rn(0.1f, m));
    }
}

// ---------------------------------------------------------------------------
extern "C" void kernel_launch(void* const* d_in, const int* in_sizes, int n_in,
                              void* d_out, int out_size) {
    const float* z  = (const float*)d_in[0];
    const float* cb = (const float*)d_in[1];
    // Guard against swapped metadata order (z has 4194304 elems, cb 2097152)
    if (n_in >= 2 && in_sizes[0] == Kk * Dd && in_sizes[1] == NEL) {
        const float* tmp = z; z = cb; cb = tmp;
    }
    float* out = (float*)d_out;

    init_kernel<<<(NQ + 255) / 256, 256>>>();
    zz_kernel<<<(NQ + 255) / 256, 256>>>(z);
    cc_kernel<<<(Kk + 255) / 256, 256>>>(cb);

    dim3 grid(Kk / 128, NQ / 128);   // 64 x 128 = 8192 blocks
    gemm_argmin_kernel<<<grid, 256>>>(z, cb);

    gather_kernel<<<(NEL + 255) / 256, 256>>>(z, cb, out, out_size);
    finalize_kernel<<<(NQ + 255) / 256, 256>>>(out, out_size);
}

// round 4
// speedup vs baseline: 1.7853x; 1.7853x over previous
#include <cuda_runtime.h>
#include <cuda_bf16.h>
#include <cstdint>

// Problem constants
#define Bq 8
#define Dd 256
#define Tt 2048
#define Kk 8192
#define NQ (Bq * Tt)          // 16384 queries
#define NEL (Bq * Dd * Tt)    // 4194304 z elements
#define NGRP (Kk / 8)         // 1024 groups of 8 codes

#define EPS 0.05f
#define CAND_CAP (4 * 1024 * 1024)

// Phase-1 tiling
#define PM 128
#define PN 128
#define PK 32
#define ROWB 40               // smem row = 40 bf16 = 80 B (bank-conflict-free ldmatrix)

// Device scratch (static; allocation is forbidden)
__device__ __align__(128) float         g_zt[NQ * Dd];     // z transposed [q][d] fp32
__device__ __align__(128) __nv_bfloat16 g_zbf[NQ * Dd];    // bf16 copy
__device__ __align__(128) __nv_bfloat16 g_cbbf[Kk * Dd];   // codebook bf16
__device__ __align__(128) float         g_gmin[(size_t)NGRP * NQ]; // per-(group,query) approx min
__device__ __align__(128) float         g_zz[NQ];
__device__ __align__(128) float         g_cc[Kk];
__device__ __align__(128) unsigned long long g_key[NQ];    // packed (dbits<<32)|k exact
__device__ __align__(128) unsigned int  g_cand[CAND_CAP];  // (q<<10)|g
__device__ int    g_ncand;
__device__ double g_loss_sum;

// ---------------------------------------------------------------------------
__device__ __forceinline__ uint32_t smem_u32(const void* p) {
    uint32_t a;
    asm("{ .reg .u64 t; cvta.to.shared.u64 t, %1; cvt.u32.u64 %0, t; }" : "=r"(a) : "l"(p));
    return a;
}
#define CP16(dst, src) \
    asm volatile("cp.async.cg.shared.global [%0], [%1], 16;" :: "r"(dst), "l"(src) : "memory")
#define LDM4(r0, r1, r2, r3, a) \
    asm volatile("ldmatrix.sync.aligned.m8n8.x4.shared.b16 {%0,%1,%2,%3}, [%4];" \
        : "=r"(r0), "=r"(r1), "=r"(r2), "=r"(r3) : "r"(a))
#define MMA16816(c0, c1, c2, c3, a0, a1, a2, a3, b0, b1) \
    asm volatile("mma.sync.aligned.m16n8k16.row.col.f32.bf16.bf16.f32 " \
        "{%0,%1,%2,%3}, {%4,%5,%6,%7}, {%8,%9}, {%0,%1,%2,%3};" \
        : "+f"(c0), "+f"(c1), "+f"(c2), "+f"(c3) \
        : "r"(a0), "r"(a1), "r"(a2), "r"(a3), "r"(b0), "r"(b1))

// ---------------------------------------------------------------------------
__global__ void init_kernel() {
    int i = blockIdx.x * blockDim.x + threadIdx.x;
    if (i < NQ) g_key[i] = ~0ull;
    if (i == 0) { g_loss_sum = 0.0; g_ncand = 0; }
}

// Exact sequential fp32 sums of squares (validated in R1)
__global__ void zz_kernel(const float* __restrict__ z) {
    int i = blockIdx.x * blockDim.x + threadIdx.x;
    if (i >= NQ) return;
    int b = i / Tt, t = i % Tt;
    const float* p = z + (size_t)b * Dd * Tt + t;
    float acc = 0.0f;
    for (int d = 0; d < Dd; d++) {
        float v = p[(size_t)d * Tt];
        acc = __fadd_rn(acc, __fmul_rn(v, v));
    }
    g_zz[i] = acc;
}
__global__ void cc_kernel(const float* __restrict__ cb) {
    int k = blockIdx.x * blockDim.x + threadIdx.x;
    if (k >= Kk) return;
    const float* p = cb + (size_t)k * Dd;
    float acc = 0.0f;
    for (int d = 0; d < Dd; d++) {
        float v = p[d];
        acc = __fadd_rn(acc, __fmul_rn(v, v));
    }
    g_cc[k] = acc;
}

__global__ void prep_cb_kernel(const float* __restrict__ cb) {
    int i = blockIdx.x * blockDim.x + threadIdx.x;
    if (i < Kk * Dd) g_cbbf[i] = __float2bfloat16(cb[i]);
}

// Transpose z (B,D,T) -> [q][d]; write fp32 + bf16 copies.
__global__ void prep_z_kernel(const float* __restrict__ z) {
    __shared__ float tile[32][33];
    int b = blockIdx.z, t0 = blockIdx.x * 32, d0 = blockIdx.y * 32;
    int tx = threadIdx.x, ty = threadIdx.y;   // 32 x 8
    #pragma unroll
    for (int r = 0; r < 4; r++) {
        int d = d0 + ty + r * 8;
        tile[ty + r * 8][tx] = z[(size_t)b * Dd * Tt + (size_t)d * Tt + t0 + tx];
    }
    __syncthreads();
    #pragma unroll
    for (int r = 0; r < 4; r++) {
        int tt = t0 + ty + r * 8;
        float v = tile[tx][ty + r * 8];
        size_t o = (size_t)(b * Tt + tt) * Dd + d0 + tx;
        g_zt[o] = v;
        g_zbf[o] = __float2bfloat16(v);
    }
}

// ---------------------------------------------------------------------------
// Phase 1: bf16 mma.sync GEMM, epilogue = per-(query, 8-code-group) approx min.
// CTA: 128q x 128k, K=256 in 8 chunks of 32, cp.async double buffer.
// 8 warps in 4(m) x 2(n); warp tile 32x64 -> frags 2(m) x 8(n).
__global__ void __launch_bounds__(256, 2) phase1_kernel() {
    __shared__ __nv_bfloat16 sA[2][PM * ROWB];
    __shared__ __nv_bfloat16 sB[2][PN * ROWB];

    int tid = threadIdx.x, wid = tid >> 5, l = tid & 31;
    int wm = wid & 3, wn = wid >> 2;
    int q0 = blockIdx.y * PM, k0 = blockIdx.x * PN;

    float acc[2][8][4];
    #pragma unroll
    for (int mi = 0; mi < 2; mi++)
        #pragma unroll
        for (int ni = 0; ni < 8; ni++)
            #pragma unroll
            for (int j = 0; j < 4; j++) acc[mi][ni][j] = 0.0f;

    // cp.async thread mapping: 2 A + 2 B 16B-chunks per thread per stage
    int arow[2], ac4[2];
    #pragma unroll
    for (int i = 0; i < 2; i++) {
        int idx = tid + i * 256;
        arow[i] = idx >> 2; ac4[i] = idx & 3;
    }
    uint32_t sA0 = smem_u32(&sA[0][0]), sB0 = smem_u32(&sB[0][0]);
    const uint32_t stgA = PM * ROWB * 2, stgB = PN * ROWB * 2;

    // ldmatrix per-lane base offsets (bytes, within a stage)
    int rA = wm * 32 + (l & 15), hA = (l >> 4) & 1;          // + mi*16 rows
    int rB = wn * 64 + (l & 15), hB = (l >> 4) & 1;          // + p*16 rows
    uint32_t aoff = (uint32_t)(rA * ROWB + hA * 8) * 2;
    uint32_t boff = (uint32_t)(rB * ROWB + hB * 8) * 2;

    auto issue = [&](int c) {
        int s = c & 1, d0 = c * PK;
        #pragma unroll
        for (int i = 0; i < 2; i++) {
            uint32_t da = sA0 + s * stgA + (uint32_t)(arow[i] * ROWB + ac4[i] * 8) * 2;
            const __nv_bfloat16* ga = g_zbf + (size_t)(q0 + arow[i]) * Dd + d0 + ac4[i] * 8;
            CP16(da, ga);
            uint32_t db = sB0 + s * stgB + (uint32_t)(arow[i] * ROWB + ac4[i] * 8) * 2;
            const __nv_bfloat16* gb = g_cbbf + (size_t)(k0 + arow[i]) * Dd + d0 + ac4[i] * 8;
            CP16(db, gb);
        }
        asm volatile("cp.async.commit_group;" ::: "memory");
    };

    issue(0);
    for (int c = 0; c < 8; c++) {
        if (c + 1 < 8) {
            issue(c + 1);
            asm volatile("cp.async.wait_group 1;" ::: "memory");
        } else {
            asm volatile("cp.async.wait_group 0;" ::: "memory");
        }
        __syncthreads();
        int s = c & 1;
        uint32_t bA = sA0 + s * stgA, bB = sB0 + s * stgB;
        #pragma unroll
        for (int ks = 0; ks < 2; ks++) {
            uint32_t a_frag[2][4], bm[4][4];
            #pragma unroll
            for (int mi = 0; mi < 2; mi++)
                LDM4(a_frag[mi][0], a_frag[mi][1], a_frag[mi][2], a_frag[mi][3],
                     bA + aoff + (uint32_t)(mi * 16 * ROWB + ks * 16) * 2);
            #pragma unroll
            for (int p = 0; p < 4; p++)
                LDM4(bm[p][0], bm[p][1], bm[p][2], bm[p][3],
                     bB + boff + (uint32_t)(p * 16 * ROWB + ks * 16) * 2);
            #pragma unroll
            for (int mi = 0; mi < 2; mi++)
                #pragma unroll
                for (int p = 0; p < 4; p++) {
                    MMA16816(acc[mi][2*p][0], acc[mi][2*p][1], acc[mi][2*p][2], acc[mi][2*p][3],
                             a_frag[mi][0], a_frag[mi][1], a_frag[mi][2], a_frag[mi][3],
                             bm[p][0], bm[p][2]);
                    MMA16816(acc[mi][2*p+1][0], acc[mi][2*p+1][1], acc[mi][2*p+1][2], acc[mi][2*p+1][3],
                             a_frag[mi][0], a_frag[mi][1], a_frag[mi][2], a_frag[mi][3],
                             bm[p][1], bm[p][3]);
                }
        }
        __syncthreads();
    }

    // Epilogue: approx d; min over each 8-code group; write g_gmin[g][q]
    int gq = l >> 2, gc = (l & 3) * 2;
    #pragma unroll
    for (int mi = 0; mi < 2; mi++) {
        int row = q0 + wm * 32 + mi * 16 + gq;
        float zz0 = g_zz[row], zz8 = g_zz[row + 8];
        #pragma unroll
        for (int ni = 0; ni < 8; ni++) {
            int col = k0 + wn * 64 + ni * 8 + gc;
            float cc0 = g_cc[col], cc1 = g_cc[col + 1];
            float m0 = fminf(zz0 - 2.0f * acc[mi][ni][0] + cc0,
                             zz0 - 2.0f * acc[mi][ni][1] + cc1);
            float m8 = fminf(zz8 - 2.0f * acc[mi][ni][2] + cc0,
                             zz8 - 2.0f * acc[mi][ni][3] + cc1);
            m0 = fminf(m0, __shfl_xor_sync(~0u, m0, 1));
            m0 = fminf(m0, __shfl_xor_sync(~0u, m0, 2));
            m8 = fminf(m8, __shfl_xor_sync(~0u, m8, 1));
            m8 = fminf(m8, __shfl_xor_sync(~0u, m8, 2));
            if ((l & 3) == 0) {
                size_t g = (size_t)((k0 + wn * 64 + ni * 8) >> 3);
                g_gmin[g * NQ + row] = m0;
                g_gmin[g * NQ + row + 8] = m8;
            }
        }
    }
}

// ---------------------------------------------------------------------------
// Phase 2a: per query, m1 = min over groups; flag groups with d <= m1 + EPS.
// CTA: 256 threads = 8 warps, 32 queries (lane = query, warp strides groups).
__global__ void __launch_bounds__(256) cand_kernel() {
    __shared__ float wmin[8][32];
    int q0 = blockIdx.x * 32;
    int wid = threadIdx.x >> 5, l = threadIdx.x & 31;
    int q = q0 + l;
    float best = 3.4e38f;
    for (int g = wid; g < NGRP; g += 8) {
        float v = g_gmin[(size_t)g * NQ + q];
        best = fminf(best, v);
    }
    wmin[wid][l] = best;
    __syncthreads();
    if (wid == 0) {
        #pragma unroll
        for (int w = 1; w < 8; w++) best = fminf(best, wmin[w][l]);
        wmin[0][l] = best;
    }
    __syncthreads();
    float thr = wmin[0][l] + EPS;
    for (int g = wid; g < NGRP; g += 8) {
        float v = g_gmin[(size_t)g * NQ + q];
        if (v <= thr) {
            int pos = atomicAdd(&g_ncand, 1);
            if (pos < CAND_CAP) g_cand[pos] = ((unsigned)q << 10) | (unsigned)g;
        }
    }
}

// Phase 2b: exact fp32 rescore of flagged groups; packed atomicMin => argmin
// with first-index tie-break (reference rounding formula, R1-validated).
__global__ void __launch_bounds__(256) rescore_kernel(const float* __restrict__ cb) {
    int gw = (blockIdx.x * blockDim.x + threadIdx.x) >> 5;
    int l = threadIdx.x & 31;
    int nwarps = (gridDim.x * blockDim.x) >> 5;
    int n = g_ncand; if (n > CAND_CAP) n = CAND_CAP;
    for (int c = gw; c < n; c += nwarps) {
        unsigned e = g_cand[c];
        int q = e >> 10, g = e & 1023;
        const float* zr = g_zt + (size_t)q * Dd;
        float zzv = g_zz[q];
        unsigned long long best = ~0ull;
        #pragma unroll 1
        for (int kk = 0; kk < 8; kk++) {
            int k = g * 8 + kk;
            const float* cr = cb + (size_t)k * Dd;
            float p = 0.0f;
            #pragma unroll
            for (int j = 0; j < 8; j++) {
                int d = l * 8 + j;
                p = __fadd_rn(p, __fmul_rn(zr[d], cr[d]));
            }
            #pragma unroll
            for (int o = 16; o > 0; o >>= 1)
                p = __fadd_rn(p, __shfl_xor_sync(~0u, p, o));
            float dd = __fadd_rn(__fadd_rn(zzv, __fmul_rn(-2.0f, p)), g_cc[k]);
            unsigned long long key =
                ((unsigned long long)__float_as_uint(dd) << 32) | (unsigned)k;
            if (key < best) best = key;
        }
        if (l == 0) atomicMin(&g_key[q], best);
    }
}

// ---------------------------------------------------------------------------
__global__ void gather_kernel(const float* __restrict__ z,
                              const float* __restrict__ cb,
                              float* __restrict__ out, int out_size) {
    __shared__ double ssum[256];
    int id = blockIdx.x * blockDim.x + threadIdx.x;
    double local = 0.0;
    if (id < NEL) {
        int t = id % Tt;
        int d = (id / Tt) % Dd;
        int b = id / (Tt * Dd);
        int i = b * Tt + t;
        int idx = (int)(unsigned)(g_key[i] & 0xffffffffu);
        float zv = z[id];
        float zq = cb[(size_t)idx * Dd + d];
        float diff = __fadd_rn(zq, -zv);
        if (id < out_size) out[id] = __fadd_rn(zv, diff);
        local = (double)__fmul_rn(diff, diff);
    }
    ssum[threadIdx.x] = local;
    __syncthreads();
    for (int s = 128; s > 0; s >>= 1) {
        if (threadIdx.x < s) ssum[threadIdx.x] += ssum[threadIdx.x + s];
        __syncthreads();
    }
    if (threadIdx.x == 0) atomicAdd(&g_loss_sum, ssum[0]);
}

__global__ void finalize_kernel(float* __restrict__ out, int out_size) {
    int i = blockIdx.x * blockDim.x + threadIdx.x;
    if (out_size >= NEL + NQ && i < NQ)
        out[NEL + i] = (float)(unsigned)(g_key[i] & 0xffffffffu);
    if (i == 0 && out_size >= NEL + NQ + 1) {
        float m = (float)(g_loss_sum / (double)NEL);
        out[NEL + NQ] = __fadd_rn(m, __fmul_rn(0.1f, m));
    }
}

// ---------------------------------------------------------------------------
extern "C" void kernel_launch(void* const* d_in, const int* in_sizes, int n_in,
                              void* d_out, int out_size) {
    const float* z  = (const float*)d_in[0];
    const float* cb = (const float*)d_in[1];
    if (n_in >= 2 && in_sizes[0] == Kk * Dd && in_sizes[1] == NEL) {
        const float* tmp = z; z = cb; cb = tmp;
    }
    float* out = (float*)d_out;

    init_kernel<<<(NQ + 255) / 256, 256>>>();
    zz_kernel<<<(NQ + 255) / 256, 256>>>(z);
    cc_kernel<<<(Kk + 255) / 256, 256>>>(cb);
    prep_cb_kernel<<<(Kk * Dd + 255) / 256, 256>>>(cb);
    dim3 tb(32, 8), tg(Tt / 32, Dd / 32, Bq);
    prep_z_kernel<<<tg, tb>>>(z);

    dim3 g1(Kk / PN, NQ / PM);   // 64 x 128
    phase1_kernel<<<g1, 256>>>();

    cand_kernel<<<NQ / 32, 256>>>();
    rescore_kernel<<<512, 256>>>(cb);

    gather_kernel<<<(NEL + 255) / 256, 256>>>(z, cb, out, out_size);
    finalize_kernel<<<(NQ + 255) / 256, 256>>>(out, out_size);
}

// round 5
// speedup vs baseline: 3.8181x; 2.1386x over previous
#include <cuda_runtime.h>
#include <cuda_fp16.h>
#include <cstdint>

// Problem constants
#define Bq 8
#define Dd 256
#define Tt 2048
#define Kk 8192
#define NQ (Bq * Tt)          // 16384 queries
#define NEL (Bq * Dd * Tt)    // 4194304 z elements
#define NGRP (Kk / 8)         // 1024 groups of 8 codes

#define EPS 0.006f
#define CAND_CAP (2 * 1024 * 1024)

// Phase-1 tiling
#define PM 128
#define PN 128
#define PK 32
#define ROWB 40               // smem row = 40 halves = 80 B (conflict-free ldmatrix)

// Device scratch (static; runtime allocation is forbidden)
__device__ __align__(128) float  g_zt[NQ * Dd];     // z transposed [q][d] fp32
__device__ __align__(128) __half g_zhf[NQ * Dd];    // fp16 copy
__device__ __align__(128) __half g_cbhf[Kk * Dd];   // codebook * 256, fp16
__device__ __align__(128) float  g_gmin[(size_t)NGRP * NQ]; // per-(group,query) approx (cc-2dot)
__device__ __align__(128) float  g_zz[NQ];
__device__ __align__(128) float  g_cc[Kk];
__device__ __align__(128) unsigned long long g_key[NQ];    // packed (dbits<<32)|k exact
__device__ __align__(128) unsigned int g_cand[CAND_CAP];   // (q<<10)|g
__device__ int    g_ncand;
__device__ double g_loss_sum;

// ---------------------------------------------------------------------------
__device__ __forceinline__ uint32_t smem_u32(const void* p) {
    uint32_t a;
    asm("{ .reg .u64 t; cvta.to.shared.u64 t, %1; cvt.u32.u64 %0, t; }" : "=r"(a) : "l"(p));
    return a;
}
#define CP16(dst, src) \
    asm volatile("cp.async.cg.shared.global [%0], [%1], 16;" :: "r"(dst), "l"(src) : "memory")
#define LDM4(r0, r1, r2, r3, a) \
    asm volatile("ldmatrix.sync.aligned.m8n8.x4.shared.b16 {%0,%1,%2,%3}, [%4];" \
        : "=r"(r0), "=r"(r1), "=r"(r2), "=r"(r3) : "r"(a))
#define MMA16816(c0, c1, c2, c3, a0, a1, a2, a3, b0, b1) \
    asm volatile("mma.sync.aligned.m16n8k16.row.col.f32.f16.f16.f32 " \
        "{%0,%1,%2,%3}, {%4,%5,%6,%7}, {%8,%9}, {%0,%1,%2,%3};" \
        : "+f"(c0), "+f"(c1), "+f"(c2), "+f"(c3) \
        : "r"(a0), "r"(a1), "r"(a2), "r"(a3), "r"(b0), "r"(b1))

// ---------------------------------------------------------------------------
__global__ void init_kernel() {
    int i = blockIdx.x * blockDim.x + threadIdx.x;
    if (i < NQ) g_key[i] = ~0ull;
    if (i == 0) { g_loss_sum = 0.0; g_ncand = 0; }
}

// Exact sequential fp32 sums of squares (rounding order validated in R1)
__global__ void zz_kernel(const float* __restrict__ z) {
    int i = blockIdx.x * blockDim.x + threadIdx.x;
    if (i >= NQ) return;
    int b = i / Tt, t = i % Tt;
    const float* p = z + (size_t)b * Dd * Tt + t;
    float acc = 0.0f;
    for (int d = 0; d < Dd; d++) {
        float v = p[(size_t)d * Tt];
        acc = __fadd_rn(acc, __fmul_rn(v, v));
    }
    g_zz[i] = acc;
}
__global__ void cc_kernel(const float* __restrict__ cb) {
    int k = blockIdx.x * blockDim.x + threadIdx.x;
    if (k >= Kk) return;
    const float* p = cb + (size_t)k * Dd;
    float acc = 0.0f;
    for (int d = 0; d < Dd; d++) {
        float v = p[d];
        acc = __fadd_rn(acc, __fmul_rn(v, v));
    }
    g_cc[k] = acc;
}

// codebook * 256 (exact pow2 rescale into fp16's sweet spot)
__global__ void prep_cb_kernel(const float* __restrict__ cb) {
    int i = blockIdx.x * blockDim.x + threadIdx.x;
    if (i < Kk * Dd) g_cbhf[i] = __float2half(cb[i] * 256.0f);
}

// Transpose z (B,D,T) -> [q][d]; write fp32 + fp16 copies.
__global__ void prep_z_kernel(const float* __restrict__ z) {
    __shared__ float tile[32][33];
    int b = blockIdx.z, t0 = blockIdx.x * 32, d0 = blockIdx.y * 32;
    int tx = threadIdx.x, ty = threadIdx.y;   // 32 x 8
    #pragma unroll
    for (int r = 0; r < 4; r++) {
        int d = d0 + ty + r * 8;
        tile[ty + r * 8][tx] = z[(size_t)b * Dd * Tt + (size_t)d * Tt + t0 + tx];
    }
    __syncthreads();
    #pragma unroll
    for (int r = 0; r < 4; r++) {
        int tt = t0 + ty + r * 8;
        float v = tile[tx][ty + r * 8];
        size_t o = (size_t)(b * Tt + tt) * Dd + d0 + tx;
        g_zt[o] = v;
        g_zhf[o] = __float2half(v);
    }
}

// ---------------------------------------------------------------------------
// Phase 1: fp16 mma.sync GEMM; epilogue = per-(query, 8-code-group) min of
// (cc - 2*dot)  [zz dropped: constant per query, doesn't affect ordering].
// CTA: 128q x 128k, K=256 in 8 chunks of 32, cp.async double buffer.
// 8 warps in 4(m) x 2(n); warp tile 32x64 -> frags 2(m) x 8(n).
__global__ void __launch_bounds__(256, 2) phase1_kernel() {
    __shared__ __half sA[2][PM * ROWB];
    __shared__ __half sB[2][PN * ROWB];

    int tid = threadIdx.x, wid = tid >> 5, l = tid & 31;
    int wm = wid & 3, wn = wid >> 2;
    int q0 = blockIdx.y * PM, k0 = blockIdx.x * PN;

    float acc[2][8][4];
    #pragma unroll
    for (int mi = 0; mi < 2; mi++)
        #pragma unroll
        for (int ni = 0; ni < 8; ni++)
            #pragma unroll
            for (int j = 0; j < 4; j++) acc[mi][ni][j] = 0.0f;

    int arow[2], ac4[2];
    #pragma unroll
    for (int i = 0; i < 2; i++) {
        int idx = tid + i * 256;
        arow[i] = idx >> 2; ac4[i] = idx & 3;
    }
    uint32_t sA0 = smem_u32(&sA[0][0]), sB0 = smem_u32(&sB[0][0]);
    const uint32_t stgA = PM * ROWB * 2, stgB = PN * ROWB * 2;

    int rA = wm * 32 + (l & 15), hA = (l >> 4) & 1;
    int rB = wn * 64 + (l & 15), hB = (l >> 4) & 1;
    uint32_t aoff = (uint32_t)(rA * ROWB + hA * 8) * 2;
    uint32_t boff = (uint32_t)(rB * ROWB + hB * 8) * 2;

    auto issue = [&](int c) {
        int s = c & 1, d0 = c * PK;
        #pragma unroll
        for (int i = 0; i < 2; i++) {
            uint32_t da = sA0 + s * stgA + (uint32_t)(arow[i] * ROWB + ac4[i] * 8) * 2;
            const __half* ga = g_zhf + (size_t)(q0 + arow[i]) * Dd + d0 + ac4[i] * 8;
            CP16(da, ga);
            uint32_t db = sB0 + s * stgB + (uint32_t)(arow[i] * ROWB + ac4[i] * 8) * 2;
            const __half* gb = g_cbhf + (size_t)(k0 + arow[i]) * Dd + d0 + ac4[i] * 8;
            CP16(db, gb);
        }
        asm volatile("cp.async.commit_group;" ::: "memory");
    };

    issue(0);
    for (int c = 0; c < 8; c++) {
        if (c + 1 < 8) {
            issue(c + 1);
            asm volatile("cp.async.wait_group 1;" ::: "memory");
        } else {
            asm volatile("cp.async.wait_group 0;" ::: "memory");
        }
        __syncthreads();
        int s = c & 1;
        uint32_t bA = sA0 + s * stgA, bB = sB0 + s * stgB;
        #pragma unroll
        for (int ks = 0; ks < 2; ks++) {
            uint32_t a_frag[2][4], bm[4][4];
            #pragma unroll
            for (int mi = 0; mi < 2; mi++)
                LDM4(a_frag[mi][0], a_frag[mi][1], a_frag[mi][2], a_frag[mi][3],
                     bA + aoff + (uint32_t)(mi * 16 * ROWB + ks * 16) * 2);
            #pragma unroll
            for (int p = 0; p < 4; p++)
                LDM4(bm[p][0], bm[p][1], bm[p][2], bm[p][3],
                     bB + boff + (uint32_t)(p * 16 * ROWB + ks * 16) * 2);
            #pragma unroll
            for (int mi = 0; mi < 2; mi++)
                #pragma unroll
                for (int p = 0; p < 4; p++) {
                    MMA16816(acc[mi][2*p][0], acc[mi][2*p][1], acc[mi][2*p][2], acc[mi][2*p][3],
                             a_frag[mi][0], a_frag[mi][1], a_frag[mi][2], a_frag[mi][3],
                             bm[p][0], bm[p][2]);
                    MMA16816(acc[mi][2*p+1][0], acc[mi][2*p+1][1], acc[mi][2*p+1][2], acc[mi][2*p+1][3],
                             a_frag[mi][0], a_frag[mi][1], a_frag[mi][2], a_frag[mi][3],
                             bm[p][1], bm[p][3]);
                }
        }
        __syncthreads();
    }

    // Epilogue: v = cc - 2*dot = fma(acc, -2^-7, cc)  (acc = dot*256)
    int gq = l >> 2;
    #pragma unroll
    for (int mi = 0; mi < 2; mi++) {
        int row = q0 + wm * 32 + mi * 16 + gq;
        #pragma unroll
        for (int ni = 0; ni < 8; ni++) {
            int col = k0 + wn * 64 + ni * 8 + (l & 3) * 2;
            float cc0 = g_cc[col], cc1 = g_cc[col + 1];
            float m0 = fminf(fmaf(acc[mi][ni][0], -0.0078125f, cc0),
                             fmaf(acc[mi][ni][1], -0.0078125f, cc1));
            float m8 = fminf(fmaf(acc[mi][ni][2], -0.0078125f, cc0),
                             fmaf(acc[mi][ni][3], -0.0078125f, cc1));
            m0 = fminf(m0, __shfl_xor_sync(~0u, m0, 1));
            m0 = fminf(m0, __shfl_xor_sync(~0u, m0, 2));
            m8 = fminf(m8, __shfl_xor_sync(~0u, m8, 1));
            m8 = fminf(m8, __shfl_xor_sync(~0u, m8, 2));
            if ((l & 3) == 0) {
                size_t g = (size_t)((k0 + wn * 64 + ni * 8) >> 3);
                g_gmin[g * NQ + row] = m0;
                g_gmin[g * NQ + row + 8] = m8;
            }
        }
    }
}

// ---------------------------------------------------------------------------
// Phase 2a: per query, m1 = min over groups; flag groups with v <= m1 + EPS.
__global__ void __launch_bounds__(256) cand_kernel() {
    __shared__ float wmin[8][32];
    int q0 = blockIdx.x * 32;
    int wid = threadIdx.x >> 5, l = threadIdx.x & 31;
    int q = q0 + l;
    float best = 3.4e38f;
    for (int g = wid; g < NGRP; g += 8)
        best = fminf(best, g_gmin[(size_t)g * NQ + q]);
    wmin[wid][l] = best;
    __syncthreads();
    if (wid == 0) {
        #pragma unroll
        for (int w = 1; w < 8; w++) best = fminf(best, wmin[w][l]);
        wmin[0][l] = best;
    }
    __syncthreads();
    float thr = wmin[0][l] + EPS;
    for (int g = wid; g < NGRP; g += 8) {
        if (g_gmin[(size_t)g * NQ + q] <= thr) {
            int pos = atomicAdd(&g_ncand, 1);
            if (pos < CAND_CAP) g_cand[pos] = ((unsigned)q << 10) | (unsigned)g;
        }
    }
}

// Phase 2b: exact fp32 rescore of flagged groups; packed atomicMin => argmin
// with first-index tie-break (reference rounding formula, R1-validated).
__global__ void __launch_bounds__(256) rescore_kernel(const float* __restrict__ cb) {
    int gw = (blockIdx.x * blockDim.x + threadIdx.x) >> 5;
    int l = threadIdx.x & 31;
    int nwarps = (gridDim.x * blockDim.x) >> 5;
    int n = g_ncand; if (n > CAND_CAP) n = CAND_CAP;
    for (int c = gw; c < n; c += nwarps) {
        unsigned e = g_cand[c];
        int q = e >> 10, g = e & 1023;
        const float* zr = g_zt + (size_t)q * Dd;
        float zzv = g_zz[q];
        unsigned long long best = ~0ull;
        #pragma unroll 1
        for (int kk = 0; kk < 8; kk++) {
            int k = g * 8 + kk;
            const float* cr = cb + (size_t)k * Dd;
            float p = 0.0f;
            #pragma unroll
            for (int j = 0; j < 8; j++) {
                int d = l * 8 + j;
                p = __fadd_rn(p, __fmul_rn(zr[d], cr[d]));
            }
            #pragma unroll
            for (int o = 16; o > 0; o >>= 1)
                p = __fadd_rn(p, __shfl_xor_sync(~0u, p, o));
            float dd = __fadd_rn(__fadd_rn(zzv, __fmul_rn(-2.0f, p)), g_cc[k]);
            unsigned long long key =
                ((unsigned long long)__float_as_uint(dd) << 32) | (unsigned)k;
            if (key < best) best = key;
        }
        if (l == 0) atomicMin(&g_key[q], best);
    }
}

// ---------------------------------------------------------------------------
// Gather: coalesced via smem transpose of the gathered codebook rows.
// Block = 32(t) x 8; tile covers 32 t x 32 d of one batch.
__global__ void gather_kernel(const float* __restrict__ z,
                              const float* __restrict__ cb,
                              float* __restrict__ out, long long out_size) {
    __shared__ float tile[32][33];
    __shared__ double ssum[256];
    int b = blockIdx.z, d0 = blockIdx.y * 32, t0 = blockIdx.x * 32;
    int tx = threadIdx.x, ty = threadIdx.y;
    #pragma unroll
    for (int r = 0; r < 4; r++) {
        int t = ty + r * 8;
        int q = b * Tt + t0 + t;
        int idx = (int)(unsigned)(g_key[q] & 0xffffffffu);
        tile[t][tx] = cb[(size_t)idx * Dd + d0 + tx];     // lane spans d: coalesced
    }
    __syncthreads();
    double local = 0.0;
    #pragma unroll
    for (int r = 0; r < 4; r++) {
        int d = d0 + ty + r * 8;
        long long o = ((long long)b * Dd + d) * Tt + t0 + tx;
        float zv = z[o];
        float zq = tile[tx][ty + r * 8];
        float diff = __fadd_rn(zq, -zv);
        if (o < out_size) out[o] = __fadd_rn(zv, diff);   // lane spans t: coalesced
        local += (double)__fmul_rn(diff, diff);
    }
    ssum[ty * 32 + tx] = local;
    __syncthreads();
    int tid = ty * 32 + tx;
    for (int s = 128; s > 0; s >>= 1) {
        if (tid < s) ssum[tid] += ssum[tid + s];
        __syncthreads();
    }
    if (tid == 0) atomicAdd(&g_loss_sum, ssum[0]);
}

__global__ void finalize_kernel(float* __restrict__ out, long long out_size) {
    int i = blockIdx.x * blockDim.x + threadIdx.x;
    if (out_size >= NEL + NQ && i < NQ)
        out[NEL + i] = (float)(unsigned)(g_key[i] & 0xffffffffu);
    if (i == 0 && out_size >= NEL + NQ + 1) {
        float m = (float)(g_loss_sum / (double)NEL);
        out[NEL + NQ] = __fadd_rn(m, __fmul_rn(0.1f, m));
    }
}

// ---------------------------------------------------------------------------
extern "C" void kernel_launch(void* const* d_in, const int* in_sizes, int n_in,
                              void* d_out, int out_size) {
    const float* z  = (const float*)d_in[0];
    const float* cb = (const float*)d_in[1];
    if (n_in >= 2 && in_sizes[0] == Kk * Dd && in_sizes[1] == NEL) {
        const float* tmp = z; z = cb; cb = tmp;
    }
    float* out = (float*)d_out;
    long long osz = out_size;

    // Launch order chosen so phase1 is launch index 3 (the one ncu captures).
    prep_cb_kernel<<<(Kk * Dd + 255) / 256, 256>>>(cb);                 // 0
    dim3 tb(32, 8), tg(Tt / 32, Dd / 32, Bq);
    prep_z_kernel<<<tg, tb>>>(z);                                       // 1
    cc_kernel<<<(Kk + 255) / 256, 256>>>(cb);                           // 2
    dim3 g1(Kk / PN, NQ / PM);
    phase1_kernel<<<g1, 256>>>();                                       // 3
    zz_kernel<<<(NQ + 255) / 256, 256>>>(z);                            // 4
    init_kernel<<<(NQ + 255) / 256, 256>>>();                           // 5
    cand_kernel<<<NQ / 32, 256>>>();                                    // 6
    rescore_kernel<<<512, 256>>>(cb);                                   // 7
    dim3 gg(Tt / 32, Dd / 32, Bq);
    gather_kernel<<<gg, tb>>>(z, cb, out, osz);                         // 8
    finalize_kernel<<<(NQ + 255) / 256, 256>>>(out, osz);               // 9
}